// round 15
// baseline (speedup 1.0000x reference)
#include <cuda_runtime.h>
#include <cstdint>

// Problem constants
#define B_   1024
#define T_   512
#define I_   16
#define H_   50
#define G_   200      // 4*H
#define FCD  64
#define NB   7        // rows per block -> grid 147, single wave
#define NTH  384      // 12 warps: 6 sections x 64 threads (50 active each)
#define NC1  (NB * H_)        // 350
#define NCELL (2 * NB * H_)   // 700

typedef unsigned long long ull;

// Precomputed bias-folded x-gates for layer 1: [t][b][g] (g = cls*50 + j).
// Padding covers the boundary block's over-read (rows 1024..1028).
__device__ float g_gx[(size_t)T_ * B_ * G_ + 4096];

// ---- f32x2 packed helpers (sm_103a FFMA2) ----
__device__ __forceinline__ void fma2(ull& acc, ull a, ull b) {
    asm("fma.rn.f32x2 %0, %1, %2, %0;" : "+l"(acc) : "l"(a), "l"(b));
}
__device__ __forceinline__ ull pk2(float x, float y) {
    ull r;
    asm("mov.b64 %0, {%1, %2};" : "=l"(r) : "f"(x), "f"(y));
    return r;
}
__device__ __forceinline__ float rsum(ull v) {
    float2 r;
    asm("mov.b64 {%0, %1}, %2;" : "=f"(r.x), "=f"(r.y) : "l"(v));
    return r.x + r.y;
}

// ---- fast activations: single-MUFU ex2 / rcp ----
__device__ __forceinline__ float fex2(float x) {
    float r;
    asm("ex2.approx.f32 %0, %1;" : "=f"(r) : "f"(x));
    return r;
}
__device__ __forceinline__ float frcp(float x) {
    float r;
    asm("rcp.approx.f32 %0, %1;" : "=f"(r) : "f"(x));
    return r;
}
#define LOG2E  1.4426950408889634f
__device__ __forceinline__ float sigf(float x) {
    return frcp(1.0f + fex2(-LOG2E * x));
}
__device__ __forceinline__ float tanh_f(float x) {
    return 2.0f * frcp(1.0f + fex2(-2.0f * LOG2E * x)) - 1.0f;
}

// ============================================================================
// Kernel 1: gx[t][b][g] = b_ih0[g] + b_hh0[g] + x[b,t,:] . w_ih0[g,:]
// ============================================================================
#define TT 128
__global__ __launch_bounds__(256, 4)
void xgate_kernel(const float* __restrict__ x,
                  const float* __restrict__ w_ih0,
                  const float* __restrict__ b_ih0,
                  const float* __restrict__ b_hh0) {
    __shared__ __align__(16) float xs[TT][I_];   // 8 KB
    const int b   = blockIdx.y;
    const int t0  = blockIdx.x * TT;
    const int tid = threadIdx.x;

    const float4* src = (const float4*)(x + ((size_t)b * T_ + t0) * I_);
    ((float4*)xs)[tid]       = src[tid];
    ((float4*)xs)[tid + 256] = src[tid + 256];
    __syncthreads();

    if (tid < G_) {
        ull w[8];
        #pragma unroll
        for (int k2 = 0; k2 < 8; k2++)
            w[k2] = pk2(__ldg(&w_ih0[tid * I_ + 2 * k2]),
                        __ldg(&w_ih0[tid * I_ + 2 * k2 + 1]));
        const float bias = __ldg(&b_ih0[tid]) + __ldg(&b_hh0[tid]);
        for (int tt = 0; tt < TT; tt++) {
            ull acc = pk2(bias, 0.0f);
            #pragma unroll
            for (int q = 0; q < 4; q++) {
                const ulonglong2 v = *(const ulonglong2*)&xs[tt][4 * q];
                fma2(acc, w[2 * q],     v.x);
                fma2(acc, w[2 * q + 1], v.y);
            }
            g_gx[((size_t)(t0 + tt) * B_ + b) * G_ + tid] = rsum(acc);
        }
    }
}

// ============================================================================
// Kernel 2: fused 2-layer LSTM recurrence + FC head. 384 threads, 6 sections.
// Section s = mat*2 + kh (mat: 0=Whh0.h1(+gx), 1=Wih1.h1(+bias2), 2=Whh1.h2).
// Thread (mat, kh, j<50) computes 4-gate partials over its K-half.
//
// CLASS ROTATION (branch-free init): accumulator a[c] holds gate class
// (2*kh + c) & 3, so the init values (gx / bias2, classes 2kh, 2kh+1) always
// go into a0, a1 -- no kh-branch inside the unrolled loop (round 14's branch
// cost 7 BSSY/BSYNC pairs per iter). Weight rows are permuted at load time;
// combine un-permutes with STATIC component selects:
//   kh0 partial: {x,y,z,w} = classes {i,f,g,o}
//   kh1 partial: {x,y,z,w} = classes {g,o,i,f}  (i=.z, f=.w, g=.x, o=.y)
// All h-loads go through ONE hoisted base pointer (kills the IMAD storm that
// inflated round 14's fma pipe).
// ============================================================================
__global__ __launch_bounds__(NTH, 1)
void fused_lstm_kernel(const float* __restrict__ w_hh0,  // [G, H]
                       const float* __restrict__ w_ih1,  // [G, H]
                       const float* __restrict__ w_hh1,  // [G, H]
                       const float* __restrict__ b_ih1,
                       const float* __restrict__ b_hh1,
                       const float* __restrict__ fc1_w,  // [FC, H]
                       const float* __restrict__ fc1_b,
                       const float* __restrict__ fc2_w,  // [1, FC]
                       const float* __restrict__ fc2_b,
                       float* __restrict__ out)          // [B, 1]
{
    __shared__ __align__(16) float hx[2][NB][56];     // [0]=h1, [1]=h2 (padded)
    __shared__ __align__(16) float4 p[3][2][NB][H_];  // rotated partials

    const int tid  = threadIdx.x;
    const int row0 = blockIdx.x * NB;
    const int sec  = tid >> 6;            // 0..5
    const int mat  = sec >> 1;            // 0/1/2
    const int kh   = sec & 1;             // K-half
    const int j    = tid & 63;            // unit index
    const bool isG = (j < H_);
    const int c0   = 2 * kh;

    // ---- weights: rotated class order; w[c] = row of class (c0+c)&3 ----
    // kh0 owns chunks 0..11 (k2 12,13 zero-padded); kh1 owns chunks 12..25.
    ull w[4][14];
    if (isG) {
        const float* wm = (mat == 0) ? w_hh0 : (mat == 1) ? w_ih1 : w_hh1;
        #pragma unroll
        for (int c = 0; c < 4; c++) {
            const int cls = (c0 + c) & 3;
            const int g = cls * H_ + j;
            #pragma unroll
            for (int k2 = 0; k2 < 14; k2++) {
                const int ch = 12 * kh + k2;
                const bool own = kh ? (ch >= 12 && ch < 26) : (ch < 12);
                float a0 = (own && 2 * ch     < H_) ? __ldg(&wm[g * H_ + 2 * ch])     : 0.0f;
                float a1 = (own && 2 * ch + 1 < H_) ? __ldg(&wm[g * H_ + 2 * ch + 1]) : 0.0f;
                w[c][k2] = pk2(a0, a1);
            }
        }
    }

    // ---- init values for a0, a1 (classes c0, c0+1) ----
    float2 iniv[NB];
    if (isG && mat == 1) {
        const float b0v = __ldg(&b_ih1[c0 * H_ + j])       + __ldg(&b_hh1[c0 * H_ + j]);
        const float b1v = __ldg(&b_ih1[(c0 + 1) * H_ + j]) + __ldg(&b_hh1[(c0 + 1) * H_ + j]);
        #pragma unroll
        for (int r = 0; r < NB; r++) iniv[r] = make_float2(b0v, b1v);
    } else {
        #pragma unroll
        for (int r = 0; r < NB; r++) iniv[r] = make_float2(0.0f, 0.0f);
    }
    if (isG && mat == 0) {   // gx for t=0
        #pragma unroll
        for (int r = 0; r < NB; r++) {
            const size_t base = (size_t)(row0 + r) * G_;
            iniv[r] = make_float2(__ldg(&g_gx[base + c0 * H_ + j]),
                                  __ldg(&g_gx[base + (c0 + 1) * H_ + j]));
        }
    }

    // hoisted h-load base: selects h1/h2 and this thread's K-half (quad 6*kh)
    const float* hbase = &hx[0][0][0] + (mat == 2 ? NB * 56 : 0) + 4 * (6 * kh);

    // ---- zero h buffers (pads must stay 0) ----
    for (int k = tid; k < 2 * NB * 56; k += NTH) ((float*)hx)[k] = 0.0f;

    // ---- combine ownership: cells tid and tid+384 (if < 700) ----
    float c_st[2] = {0.0f, 0.0f};
    int   cr[2], cj[2], hoff[2];
    bool  cl2[2];
    const bool has2 = (tid < NCELL - NTH);   // tid < 316
    #pragma unroll
    for (int k = 0; k < 2; k++) {
        const int cell = tid + k * NTH;
        const int c = (cell < NCELL) ? cell : 0;
        cl2[k] = (c >= NC1);
        const int rem = cl2[k] ? c - NC1 : c;
        cr[k] = rem / H_;
        cj[k] = rem - cr[k] * H_;
        hoff[k] = (cl2[k] ? NB * 56 : 0) + cr[k] * 56 + cj[k];
    }
    __syncthreads();

    for (int it = 0; it <= T_; it++) {
        // ---- gate phase ----
        if (isG) {
            // G0: prefetch next iter's gx while computing
            float2 gxn[NB];
            const bool pf = (mat == 0) && (it + 1 < T_);
            if (pf) {
                #pragma unroll
                for (int r = 0; r < NB; r++) {
                    const size_t base = ((size_t)(it + 1) * B_ + row0 + r) * G_;
                    gxn[r] = make_float2(__ldg(&g_gx[base + c0 * H_ + j]),
                                         __ldg(&g_gx[base + (c0 + 1) * H_ + j]));
                }
            }

            #pragma unroll
            for (int r = 0; r < NB; r++) {
                ull a0 = pk2(iniv[r].x, 0.0f);
                ull a1 = pk2(iniv[r].y, 0.0f);
                ull a2 = 0ull, a3 = 0ull;
                const float* hr = hbase + r * 56;

                // batch 1: local quads 0..2
                ulonglong2 v[3];
                #pragma unroll
                for (int q = 0; q < 3; q++)
                    v[q] = *(const ulonglong2*)(hr + 4 * q);
                #pragma unroll
                for (int q = 0; q < 3; q++) {
                    fma2(a0, w[0][2 * q], v[q].x);  fma2(a0, w[0][2 * q + 1], v[q].y);
                    fma2(a1, w[1][2 * q], v[q].x);  fma2(a1, w[1][2 * q + 1], v[q].y);
                    fma2(a2, w[2][2 * q], v[q].x);  fma2(a2, w[2][2 * q + 1], v[q].y);
                    fma2(a3, w[3][2 * q], v[q].x);  fma2(a3, w[3][2 * q + 1], v[q].y);
                }
                // batch 2: local quads 3..4
                #pragma unroll
                for (int q = 0; q < 2; q++)
                    v[q] = *(const ulonglong2*)(hr + 4 * (q + 3));
                #pragma unroll
                for (int q = 0; q < 2; q++) {
                    const int k2 = 2 * (q + 3);
                    fma2(a0, w[0][k2], v[q].x);  fma2(a0, w[0][k2 + 1], v[q].y);
                    fma2(a1, w[1][k2], v[q].x);  fma2(a1, w[1][k2 + 1], v[q].y);
                    fma2(a2, w[2][k2], v[q].x);  fma2(a2, w[2][k2 + 1], v[q].y);
                    fma2(a3, w[3][k2], v[q].x);  fma2(a3, w[3][k2 + 1], v[q].y);
                }
                // batch 3: local quads 5..6
                #pragma unroll
                for (int q = 0; q < 2; q++)
                    v[q] = *(const ulonglong2*)(hr + 4 * (q + 5));
                #pragma unroll
                for (int q = 0; q < 2; q++) {
                    const int k2 = 2 * (q + 5);
                    fma2(a0, w[0][k2], v[q].x);  fma2(a0, w[0][k2 + 1], v[q].y);
                    fma2(a1, w[1][k2], v[q].x);  fma2(a1, w[1][k2 + 1], v[q].y);
                    fma2(a2, w[2][k2], v[q].x);  fma2(a2, w[2][k2 + 1], v[q].y);
                    fma2(a3, w[3][k2], v[q].x);  fma2(a3, w[3][k2 + 1], v[q].y);
                }
                p[mat][kh][r][j] = make_float4(rsum(a0), rsum(a1),
                                               rsum(a2), rsum(a3));
            }

            if (pf) {
                #pragma unroll
                for (int r = 0; r < NB; r++) iniv[r] = gxn[r];
            }
        }
        __syncthreads();

        // ---- combine: 1-2 cells per thread; un-permute rotated partials ----
        #pragma unroll
        for (int k = 0; k < 2; k++) {
            const bool own = (k == 0) || has2;
            if (own) {
                const bool act = cl2[k] ? (it >= 1) : (it < T_);
                if (act) {
                    const int r = cr[k], jj = cj[k];
                    float gi, gf, gg, go;
                    if (cl2[k]) {
                        const float4 a = p[1][0][r][jj];   // classes {i,f,g,o}
                        const float4 b = p[1][1][r][jj];   // classes {g,o,i,f}
                        const float4 c = p[2][0][r][jj];
                        const float4 d = p[2][1][r][jj];
                        gi = a.x + b.z + c.x + d.z;
                        gf = a.y + b.w + c.y + d.w;
                        gg = a.z + b.x + c.z + d.x;
                        go = a.w + b.y + c.w + d.y;
                    } else {
                        const float4 a = p[0][0][r][jj];
                        const float4 b = p[0][1][r][jj];
                        gi = a.x + b.z;
                        gf = a.y + b.w;
                        gg = a.z + b.x;
                        go = a.w + b.y;
                    }
                    const float ig = sigf(gi);
                    const float fg = sigf(gf);
                    const float gv = tanh_f(gg);
                    const float og = sigf(go);
                    c_st[k] = fg * c_st[k] + ig * gv;
                    ((float*)hx)[hoff[k]] = og * tanh_f(c_st[k]);
                }
            }
        }
        __syncthreads();
    }

    // ---- FC head: warps 0-6 each handle one batch row, shfl reduction ----
    const int wid  = tid / 32;
    const int lane = tid - wid * 32;
    if (wid < NB) {
        const int row = row0 + wid;
        if (row < B_) {
            float s = 0.0f;
            #pragma unroll
            for (int uu = 0; uu < 2; uu++) {
                const int u = lane + uu * 32;
                float a = __ldg(&fc1_b[u]);
                #pragma unroll
                for (int k = 0; k < H_; k++)
                    a += __ldg(&fc1_w[u * H_ + k]) * hx[1][wid][k];
                a = fmaxf(a, 0.0f);
                s += a * __ldg(&fc2_w[u]);
            }
            #pragma unroll
            for (int off = 16; off > 0; off >>= 1)
                s += __shfl_down_sync(0xffffffffu, s, off);
            if (lane == 0) out[row] = s + __ldg(&fc2_b[0]);
        }
    }
}

extern "C" void kernel_launch(void* const* d_in, const int* in_sizes, int n_in,
                              void* d_out, int out_size) {
    const float* x     = (const float*)d_in[0];
    const float* w_ih0 = (const float*)d_in[1];
    const float* w_hh0 = (const float*)d_in[2];
    const float* b_ih0 = (const float*)d_in[3];
    const float* b_hh0 = (const float*)d_in[4];
    const float* w_ih1 = (const float*)d_in[5];
    const float* w_hh1 = (const float*)d_in[6];
    const float* b_ih1 = (const float*)d_in[7];
    const float* b_hh1 = (const float*)d_in[8];
    const float* fc1_w = (const float*)d_in[9];
    const float* fc1_b = (const float*)d_in[10];
    const float* fc2_w = (const float*)d_in[11];
    const float* fc2_b = (const float*)d_in[12];
    float* out = (float*)d_out;

    dim3 xg_grid(T_ / TT, B_);
    xgate_kernel<<<xg_grid, 256>>>(x, w_ih0, b_ih0, b_hh0);

    const int grid = (B_ + NB - 1) / NB;   // 147
    fused_lstm_kernel<<<grid, NTH>>>(
        w_hh0, w_ih1, w_hh1, b_ih1, b_hh1,
        fc1_w, fc1_b, fc2_w, fc2_b, out);
}

// round 16
// speedup vs baseline: 1.3434x; 1.3434x over previous
#include <cuda_runtime.h>
#include <cstdint>

// Problem constants
#define B_   1024
#define T_   512
#define I_   16
#define H_   50
#define G_   200      // 4*H
#define FCD  64
#define NB   7        // rows per block -> grid 147, single wave
#define NTH  384      // 12 warps: 3 sections x 128 threads (100 gate threads each)

typedef unsigned long long ull;

// Precomputed bias-folded x-gates for layer 1: [t][b][g]. Padding covers the
// boundary block's over-read (rows 1024..1028: static zeros, never output).
__device__ float g_gx[(size_t)T_ * B_ * G_ + 4096];

// ---- f32x2 packed helpers (sm_103a FFMA2) ----
__device__ __forceinline__ void fma2(ull& acc, ull a, ull b) {
    asm("fma.rn.f32x2 %0, %1, %2, %0;" : "+l"(acc) : "l"(a), "l"(b));
}
__device__ __forceinline__ ull add2(ull a, ull b) {
    ull r;
    asm("add.rn.f32x2 %0, %1, %2;" : "=l"(r) : "l"(a), "l"(b));
    return r;
}
__device__ __forceinline__ ull pk2(float x, float y) {
    ull r;
    asm("mov.b64 %0, {%1, %2};" : "=l"(r) : "f"(x), "f"(y));
    return r;
}
__device__ __forceinline__ float rsum(ull v) {
    float2 r;
    asm("mov.b64 {%0, %1}, %2;" : "=f"(r.x), "=f"(r.y) : "l"(v));
    return r.x + r.y;
}

// ---- fast activations: single-MUFU ex2 / rcp ----
__device__ __forceinline__ float fex2(float x) {
    float r;
    asm("ex2.approx.f32 %0, %1;" : "=f"(r) : "f"(x));
    return r;
}
__device__ __forceinline__ float frcp(float x) {
    float r;
    asm("rcp.approx.f32 %0, %1;" : "=f"(r) : "f"(x));
    return r;
}
#define LOG2E  1.4426950408889634f
__device__ __forceinline__ float sigf(float x) {
    return frcp(1.0f + fex2(-LOG2E * x));
}
__device__ __forceinline__ float tanh_f(float x) {
    return 2.0f * frcp(1.0f + fex2(-2.0f * LOG2E * x)) - 1.0f;
}

// ============================================================================
// Kernel 1: gx[t][b][g] = b_ih0[g] + b_hh0[g] + x[b,t,:] . w_ih0[g,:]
// ============================================================================
#define TT 128
__global__ __launch_bounds__(256, 4)
void xgate_kernel(const float* __restrict__ x,
                  const float* __restrict__ w_ih0,
                  const float* __restrict__ b_ih0,
                  const float* __restrict__ b_hh0) {
    __shared__ __align__(16) float xs[TT][I_];   // 8 KB
    const int b   = blockIdx.y;
    const int t0  = blockIdx.x * TT;
    const int tid = threadIdx.x;

    const float4* src = (const float4*)(x + ((size_t)b * T_ + t0) * I_);
    ((float4*)xs)[tid]       = src[tid];
    ((float4*)xs)[tid + 256] = src[tid + 256];
    __syncthreads();

    if (tid < G_) {
        ull w[8];
        #pragma unroll
        for (int k2 = 0; k2 < 8; k2++)
            w[k2] = pk2(__ldg(&w_ih0[tid * I_ + 2 * k2]),
                        __ldg(&w_ih0[tid * I_ + 2 * k2 + 1]));
        const float bias = __ldg(&b_ih0[tid]) + __ldg(&b_hh0[tid]);
        for (int tt = 0; tt < TT; tt++) {
            ull acc = pk2(bias, 0.0f);
            #pragma unroll
            for (int q = 0; q < 4; q++) {
                const ulonglong2 v = *(const ulonglong2*)&xs[tt][4 * q];
                fma2(acc, w[2 * q],     v.x);
                fma2(acc, w[2 * q + 1], v.y);
            }
            g_gx[((size_t)(t0 + tt) * B_ + b) * G_ + tid] = rsum(acc);
        }
    }
}

// ============================================================================
// Kernel 2: fused 2-layer LSTM recurrence + FC head. 384 threads.
// Thread layout = round 10 (best): 3 sections x 128; thread i<100 of section
// `grp` computes gates 2i, 2i+1 of matrix grp (0=Whh0.h1+gx, 1=Wih1.h1+bias2,
// 2=Whh1.h2); each broadcast h-quad LDS.128 feeds 4 FFMA2.
//
// SPLIT-ROW PIPELINE (new): rows are independent recurrences. Set X = rows
// 0-3, set Y = rows 4-6. Even phase p=2t: gate(X,t) + combine(Y,t-1); odd
// phase p=2t+1: gate(Y,t) + combine(X,t). One __syncthreads per phase (same
// barrier count as before), but each phase mixes gate FMA/LDS with the other
// set's MUFU combine -> combine latency hidden; smaller phases -> less skew.
// Sets use disjoint rows of hx / partial buffers -> no races.
// Per set, L1/L2 stagger is unchanged: gate at it computes L1 gates (t=it)
// and L2 partials; combine at it does L1 cell (if it<T) and L2 cell (if it>=1).
// ============================================================================
__global__ __launch_bounds__(NTH, 1)
void fused_lstm_kernel(const float* __restrict__ w_hh0,  // [G, H]
                       const float* __restrict__ w_ih1,  // [G, H]
                       const float* __restrict__ w_hh1,  // [G, H]
                       const float* __restrict__ b_ih1,
                       const float* __restrict__ b_hh1,
                       const float* __restrict__ fc1_w,  // [FC, H]
                       const float* __restrict__ fc1_b,
                       const float* __restrict__ fc2_w,  // [1, FC]
                       const float* __restrict__ fc2_b,
                       float* __restrict__ out)          // [B, 1]
{
    __shared__ __align__(16) float hx[2][NB][52];   // [0]=h1, [1]=h2 (padded)
    __shared__ float gl1[NB][G_];                   // L1 gates (complete)
    __shared__ float pA[NB][G_];                    // L2 partial (Wih1 part)
    __shared__ float pB[NB][G_];                    // L2 partial (Whh1 part)

    const int tid  = threadIdx.x;
    const int row0 = blockIdx.x * NB;
    const int grp  = tid >> 7;             // 0/1/2
    const int i    = tid & 127;
    const bool isG = (i < 100);            // computes gates 2i, 2i+1

    // ---- weights: two gate rows of one matrix, f32x2-packed, zero-padded ----
    ull wA[26], wB[26];
    float2 biasr = make_float2(0.0f, 0.0f);
    if (isG) {
        const float* wm = (grp == 0) ? w_hh0 : (grp == 1) ? w_ih1 : w_hh1;
        const int g0 = 2 * i, g1 = 2 * i + 1;
        #pragma unroll
        for (int k2 = 0; k2 < 26; k2++) {
            float a0 = (2 * k2     < H_) ? __ldg(&wm[g0 * H_ + 2 * k2])     : 0.0f;
            float a1 = (2 * k2 + 1 < H_) ? __ldg(&wm[g0 * H_ + 2 * k2 + 1]) : 0.0f;
            wA[k2] = pk2(a0, a1);
            float b0 = (2 * k2     < H_) ? __ldg(&wm[g1 * H_ + 2 * k2])     : 0.0f;
            float b1 = (2 * k2 + 1 < H_) ? __ldg(&wm[g1 * H_ + 2 * k2 + 1]) : 0.0f;
            wB[k2] = pk2(b0, b1);
        }
        if (grp == 1) {
            biasr.x = __ldg(&b_ih1[g0]) + __ldg(&b_hh1[g0]);
            biasr.y = __ldg(&b_ih1[g1]) + __ldg(&b_hh1[g1]);
        }
    }

    // per-row accumulator init: G0 -> gx (refreshed at its set's gate phases),
    // G1 -> bias2 (constant), G2 -> 0 (biasr is zero)
    float2 gxr[NB];
    #pragma unroll
    for (int r = 0; r < NB; r++) gxr[r] = biasr;
    if (isG && grp == 0) {
        #pragma unroll
        for (int r = 0; r < NB; r++)
            gxr[r] = *(const float2*)&g_gx[(size_t)(row0 + r) * G_ + 2 * i];  // t=0
    }

    // hoisted h base for this section's input (G2 reads h2)
    const float* hbase = &hx[0][0][0] + (grp == 2 ? NB * 52 : 0);
    float* dst = (grp == 0) ? &gl1[0][0] : (grp == 1) ? &pA[0][0] : &pB[0][0];

    // ---- zero h buffers ----
    for (int k = tid; k < 2 * NB * 52; k += NTH) ((float*)hx)[k] = 0.0f;

    // ---- combine ownership ----
    // Set X (rows 0-3, 400 cells): k0 = cell tid (always <400), k1 = tid+384 (tid<16)
    // Set Y (rows 4-6, 300 cells): cell tid (tid<300)
    float c_stX[2] = {0.0f, 0.0f};
    float c_stY = 0.0f;
    int  xoff[2], xh[2];  bool xl2[2];
    const bool hasX1 = (tid < 16);
    #pragma unroll
    for (int k = 0; k < 2; k++) {
        const int cell = tid + k * NTH;          // k1 only used when tid<16
        const int c = (cell < 400) ? cell : 0;
        xl2[k] = (c >= 200);
        const int rem = xl2[k] ? c - 200 : c;
        const int r = rem / H_;                  // 0..3
        const int j = rem - r * H_;
        xoff[k] = r * G_ + j;
        xh[k]   = (xl2[k] ? NB * 52 : 0) + r * 52 + j;
    }
    const bool hasY = (tid < 300);
    int yoff = 0, yh = 0; bool yl2 = false;
    {
        const int c = hasY ? tid : 0;
        yl2 = (c >= 150);
        const int rem = yl2 ? c - 150 : c;
        const int r = 4 + rem / H_;              // 4..6
        const int j = rem - (r - 4) * H_;
        yoff = r * G_ + j;
        yh   = (yl2 ? NB * 52 : 0) + r * 52 + j;
    }
    __syncthreads();

    // ---- phase loop ----
    for (int p = 0; p <= 2 * T_ + 2; p++) {
        const bool ev = ((p & 1) == 0);
        const int tg = ev ? (p >> 1) : ((p - 1) >> 1);   // gate time, active set
        const int tc = ev ? (p >> 1) - 1 : ((p - 1) >> 1); // combine time, other set
        const bool doGate = ev ? (tg <= T_) : (tg <= T_);
        const int rbeg = ev ? 0 : 4;
        const int rend = ev ? 4 : NB;

        // ---- gate work for the active set ----
        if (isG && doGate && p <= (ev ? 2 * T_ : 2 * T_ + 1)) {
            // G0: prefetch this set's gx for time tg+1
            float2 gxn[4];
            const bool pf = (grp == 0) && (tg + 1 < T_);
            if (pf) {
                for (int r = rbeg; r < rend; r++) {
                    const size_t base = ((size_t)(tg + 1) * B_ + row0 + r) * G_;
                    gxn[r - rbeg] = *(const float2*)&g_gx[base + 2 * i];
                }
            }

            for (int r = rbeg; r < rend; r++) {
                ull e0 = pk2(gxr[r].x, 0.0f), o0 = 0ull;
                ull e1 = pk2(gxr[r].y, 0.0f), o1 = 0ull;
                const float* hr = hbase + r * 52;

                ulonglong2 v[5];
                #pragma unroll
                for (int q = 0; q < 5; q++)
                    v[q] = *(const ulonglong2*)(hr + 4 * q);
                #pragma unroll
                for (int q = 0; q < 5; q++) {
                    fma2(e0, wA[2 * q],     v[q].x);
                    fma2(o0, wA[2 * q + 1], v[q].y);
                    fma2(e1, wB[2 * q],     v[q].x);
                    fma2(o1, wB[2 * q + 1], v[q].y);
                }
                #pragma unroll
                for (int q = 0; q < 4; q++)
                    v[q] = *(const ulonglong2*)(hr + 4 * (q + 5));
                #pragma unroll
                for (int q = 0; q < 4; q++) {
                    const int k2 = 2 * (q + 5);
                    fma2(e0, wA[k2],     v[q].x);
                    fma2(o0, wA[k2 + 1], v[q].y);
                    fma2(e1, wB[k2],     v[q].x);
                    fma2(o1, wB[k2 + 1], v[q].y);
                }
                #pragma unroll
                for (int q = 0; q < 4; q++)
                    v[q] = *(const ulonglong2*)(hr + 4 * (q + 9));
                #pragma unroll
                for (int q = 0; q < 4; q++) {
                    const int k2 = 2 * (q + 9);
                    fma2(e0, wA[k2],     v[q].x);
                    fma2(o0, wA[k2 + 1], v[q].y);
                    fma2(e1, wB[k2],     v[q].x);
                    fma2(o1, wB[k2 + 1], v[q].y);
                }
                *(float2*)&dst[r * G_ + 2 * i] =
                    make_float2(rsum(add2(e0, o0)), rsum(add2(e1, o1)));
            }

            if (pf) {
                for (int r = rbeg; r < rend; r++) gxr[r] = gxn[r - rbeg];
            }
        }

        // ---- combine work for the other set (gate order i, f, g, o) ----
        if (tc >= 0 && tc <= T_) {
            if (ev) {
                // combine set Y
                if (hasY) {
                    const bool act = yl2 ? (tc >= 1) : (tc < T_);
                    if (act) {
                        float gi, gf, gg, go;
                        if (yl2) {
                            const float* q1 = &pA[0][0];
                            const float* q2 = &pB[0][0];
                            gi = q1[yoff]          + q2[yoff];
                            gf = q1[yoff + H_]     + q2[yoff + H_];
                            gg = q1[yoff + 2 * H_] + q2[yoff + 2 * H_];
                            go = q1[yoff + 3 * H_] + q2[yoff + 3 * H_];
                        } else {
                            const float* q0 = &gl1[0][0];
                            gi = q0[yoff];
                            gf = q0[yoff + H_];
                            gg = q0[yoff + 2 * H_];
                            go = q0[yoff + 3 * H_];
                        }
                        const float ig = sigf(gi);
                        const float fg = sigf(gf);
                        const float gv = tanh_f(gg);
                        const float og = sigf(go);
                        c_stY = fg * c_stY + ig * gv;
                        ((float*)hx)[yh] = og * tanh_f(c_stY);
                    }
                }
            } else {
                // combine set X
                #pragma unroll
                for (int k = 0; k < 2; k++) {
                    const bool own = (k == 0) || hasX1;
                    if (own) {
                        const bool act = xl2[k] ? (tc >= 1) : (tc < T_);
                        if (act) {
                            const int o = xoff[k];
                            float gi, gf, gg, go;
                            if (xl2[k]) {
                                const float* q1 = &pA[0][0];
                                const float* q2 = &pB[0][0];
                                gi = q1[o]          + q2[o];
                                gf = q1[o + H_]     + q2[o + H_];
                                gg = q1[o + 2 * H_] + q2[o + 2 * H_];
                                go = q1[o + 3 * H_] + q2[o + 3 * H_];
                            } else {
                                const float* q0 = &gl1[0][0];
                                gi = q0[o];
                                gf = q0[o + H_];
                                gg = q0[o + 2 * H_];
                                go = q0[o + 3 * H_];
                            }
                            const float ig = sigf(gi);
                            const float fg = sigf(gf);
                            const float gv = tanh_f(gg);
                            const float og = sigf(go);
                            c_stX[k] = fg * c_stX[k] + ig * gv;
                            ((float*)hx)[xh[k]] = og * tanh_f(c_stX[k]);
                        }
                    }
                }
            }
        }
        __syncthreads();
    }

    // ---- FC head: warps 0-6 each handle one batch row, shfl reduction ----
    const int wid  = tid / 32;
    const int lane = tid - wid * 32;
    if (wid < NB) {
        const int row = row0 + wid;
        if (row < B_) {
            float s = 0.0f;
            #pragma unroll
            for (int uu = 0; uu < 2; uu++) {
                const int u = lane + uu * 32;
                float a = __ldg(&fc1_b[u]);
                #pragma unroll
                for (int k = 0; k < H_; k++)
                    a += __ldg(&fc1_w[u * H_ + k]) * hx[1][wid][k];
                a = fmaxf(a, 0.0f);
                s += a * __ldg(&fc2_w[u]);
            }
            #pragma unroll
            for (int off = 16; off > 0; off >>= 1)
                s += __shfl_down_sync(0xffffffffu, s, off);
            if (lane == 0) out[row] = s + __ldg(&fc2_b[0]);
        }
    }
}

extern "C" void kernel_launch(void* const* d_in, const int* in_sizes, int n_in,
                              void* d_out, int out_size) {
    const float* x     = (const float*)d_in[0];
    const float* w_ih0 = (const float*)d_in[1];
    const float* w_hh0 = (const float*)d_in[2];
    const float* b_ih0 = (const float*)d_in[3];
    const float* b_hh0 = (const float*)d_in[4];
    const float* w_ih1 = (const float*)d_in[5];
    const float* w_hh1 = (const float*)d_in[6];
    const float* b_ih1 = (const float*)d_in[7];
    const float* b_hh1 = (const float*)d_in[8];
    const float* fc1_w = (const float*)d_in[9];
    const float* fc1_b = (const float*)d_in[10];
    const float* fc2_w = (const float*)d_in[11];
    const float* fc2_b = (const float*)d_in[12];
    float* out = (float*)d_out;

    dim3 xg_grid(T_ / TT, B_);
    xgate_kernel<<<xg_grid, 256>>>(x, w_ih0, b_ih0, b_hh0);

    const int grid = (B_ + NB - 1) / NB;   // 147
    fused_lstm_kernel<<<grid, NTH>>>(
        w_hh0, w_ih1, w_hh1, b_ih1, b_hh1,
        fc1_w, fc1_b, fc2_w, fc2_b, out);
}